// round 1
// baseline (speedup 1.0000x reference)
#include <cuda_runtime.h>
#include <math.h>

#define N_Q 6
#define NSTATE 64
#define SEQ 512
#define BATCH 256
#define PI_F 3.14159265358979323846f

// ---------------- device-global precomputed tables ----------------
__device__ float2 g_Upack[32 * 128];   // U[k][j]: entry for thread tid=(k<<1)|half, jj: g_Upack[jj*128+tid] = U[tid>>1][(tid&1)*32+jj]
__device__ float  g_A[NSTATE * N_Q];   // QSVT phase coefficients per (output index, qubit)
__device__ int    g_src[NSTATE];       // QSVT source permutation
__device__ float  g_Mdt[36];           // Wdt @ Wx[0:3]  (6x6)
__device__ float  g_Mcw[108];          // Wc  @ Wx[9:15] (18x6)

__device__ __forceinline__ float2 cmulf(float2 a, float2 b) {
    return make_float2(a.x * b.x - a.y * b.y, a.x * b.y + a.y * b.x);
}
__device__ __forceinline__ float2 caddf(float2 a, float2 b) {
    return make_float2(a.x + b.x, a.y + b.y);
}

// ---------------- setup kernel: build U, QSVT tables, folded matrices ----------------
__global__ void qm_setup(const float* __restrict__ Wx,      // (15,6)
                         const float* __restrict__ Wdt,     // (6,3)
                         const float* __restrict__ poly,    // (4)
                         const float* __restrict__ qsvt,    // (18)
                         const float* __restrict__ cp,      // (60)
                         const float* __restrict__ Wc)      // (18,6)
{
    __shared__ float2 M[NSTATE][NSTATE];   // 32 KB, ansatz matrix accumulator
    const int tid = threadIdx.x;           // 128 threads

    // --- Mdt[w][v] = sum_r Wdt[w,r] * Wx[r,v] ---
    if (tid < 36) {
        int w = tid / 6, v = tid % 6;
        float acc = 0.f;
        for (int r = 0; r < 3; r++) acc = fmaf(Wdt[w * 3 + r], Wx[r * 6 + v], acc);
        g_Mdt[tid] = acc;
    }
    // --- Mcw[j][v] = sum_w Wc[j,w] * Wx[9+w, v] ---
    if (tid < 108) {
        int j = tid / 6, v = tid % 6;
        float acc = 0.f;
        for (int w = 0; w < 6; w++) acc = fmaf(Wc[j * 6 + w], Wx[(9 + w) * 6 + v], acc);
        g_Mcw[tid] = acc;
    }
    // --- QSVT backward index tracking ---
    if (tid < NSTATE) {
        const int chc[11] = {0, 1, 2, 3, 4, 5, 5, 4, 3, 2, 1};
        const int cht[11] = {1, 2, 3, 4, 5, 0, 4, 3, 2, 1, 0};
        int k = tid;
        float A[N_Q] = {0.f, 0.f, 0.f, 0.f, 0.f, 0.f};
        for (int deg = 3; deg >= 0; --deg) {
            // invert the CNOT chain (process in reverse order; CNOT map is own inverse form)
            for (int ci = 10; ci >= 0; --ci) {
                int c = chc[ci], t = cht[ci];
                k ^= ((k >> (5 - c)) & 1) << (5 - t);
            }
            float coeff = poly[deg];
            for (int w = 0; w < N_Q; w++) {
                float wgt = (deg < 3) ? qsvt[deg * 6 + w] : 1.0f;
                float b = (float)((k >> (5 - w)) & 1);
                A[w] += 0.5f * (1.0f - 2.0f * b) * coeff * wgt * PI_F;
            }
        }
        g_src[tid] = k;
        for (int w = 0; w < N_Q; w++) g_A[tid * N_Q + w] = A[w];
    }

    // --- build ansatz U = product of gates applied to identity (left-multiply) ---
    for (int i = tid; i < NSTATE * NSTATE; i += 128) {
        int r = i >> 6, c = i & 63;
        M[r][c] = make_float2(r == c ? 1.f : 0.f, 0.f);
    }
    __syncthreads();

    auto apply1 = [&](int tq, float2 g00, float2 g01, float2 g10, float2 g11, int ctrl) {
        int m = 1 << (5 - tq);
        for (int idx = tid; idx < 32 * 64; idx += 128) {
            int col = idx & 63, pr = idx >> 6;
            int low = pr & (m - 1);
            int k0 = ((pr & ~(m - 1)) << 1) | low;
            int k1 = k0 | m;
            if (ctrl >= 0 && !((k0 >> (5 - ctrl)) & 1)) continue;
            float2 a0 = M[k0][col], a1 = M[k1][col];
            M[k0][col] = caddf(cmulf(g00, a0), cmulf(g01, a1));
            M[k1][col] = caddf(cmulf(g10, a0), cmulf(g11, a1));
        }
        __syncthreads();
    };

    int p = 0;
    for (int layer = 0; layer < 2; ++layer) {
        for (int i = 0; i < N_Q; i++) {
            float thx = cp[p], thy = cp[p + 1], thz = cp[p + 2];
            p += 3;
            float c, s;
            c = cosf(0.5f * thx); s = sinf(0.5f * thx);
            apply1(i, make_float2(c, 0), make_float2(0, -s), make_float2(0, -s), make_float2(c, 0), -1);
            c = cosf(0.5f * thy); s = sinf(0.5f * thy);
            apply1(i, make_float2(c, 0), make_float2(-s, 0), make_float2(s, 0), make_float2(c, 0), -1);
            c = cosf(0.5f * thz); s = sinf(0.5f * thz);
            apply1(i, make_float2(c, -s), make_float2(0, 0), make_float2(0, 0), make_float2(c, s), -1);
        }
        for (int i = 0; i < N_Q; i++) {
            float th = cp[p++];
            float c = cosf(0.5f * th), s = sinf(0.5f * th);
            apply1((i + 1) % N_Q, make_float2(c, 0), make_float2(0, -s), make_float2(0, -s), make_float2(c, 0), i);
        }
        for (int i = N_Q - 1; i >= 0; i--) {
            float th = cp[p++];
            float c = cosf(0.5f * th), s = sinf(0.5f * th);
            apply1((i + 5) % N_Q, make_float2(c, 0), make_float2(0, -s), make_float2(0, -s), make_float2(c, 0), i);
        }
    }

    // pack U for the main kernel's register layout
    for (int jj = 0; jj < 32; jj++) {
        g_Upack[jj * 128 + tid] = M[tid >> 1][((tid & 1) << 5) + jj];
    }
}

// ---------------- main kernel: one CTA per batch element, 512-step scan ----------------
__global__ void __launch_bounds__(128) qm_main(const float* __restrict__ angles,
                                               const float* __restrict__ bdt,
                                               const float* __restrict__ D,
                                               float* __restrict__ out)
{
    __shared__ float2 s_sh[NSTATE];    // interleaved: s_sh[(j&31)*2 + (j>>5)] = s[j]
    __shared__ float2 a_sh[NSTATE];
    __shared__ float  A_sT[N_Q * NSTATE];   // transposed: A_sT[w*64 + j]
    __shared__ int    src_s[NSTATE];
    __shared__ float  Mdt_s[36], Mcw_s[108], bdt_s[N_Q], D_s[18];
    __shared__ float  ang_s[8], dts_s[8], hc_s[8], hs_s[8], pc_s[8], ps_s[8], h_s[8];
    __shared__ float  red_s[2][18];

    const int tid = threadIdx.x;
    const int b   = blockIdx.x;

    // load U rows into registers (coalesced)
    float2 ureg[32];
#pragma unroll
    for (int jj = 0; jj < 32; jj++) ureg[jj] = g_Upack[jj * 128 + tid];

    if (tid < NSTATE) {
        src_s[tid] = g_src[tid];
#pragma unroll
        for (int w = 0; w < N_Q; w++) A_sT[w * NSTATE + tid] = g_A[tid * N_Q + w];
    }
    if (tid < 36)  Mdt_s[tid] = g_Mdt[tid];
    if (tid < 108) Mcw_s[tid] = g_Mcw[tid];
    if (tid < N_Q) { bdt_s[tid] = bdt[tid]; h_s[tid] = 0.f; }
    if (tid < 18)  D_s[tid] = D[tid];

    const float* angb = angles + (size_t)b * SEQ * N_Q;
    float angv = (tid < N_Q) ? angb[tid] : 0.f;   // prefetched angle for current t
    __syncthreads();

    for (int t = 0; t < SEQ; ++t) {
        // ---- Phase A: per-step scalars (warp 0) ----
        if (tid < 32) {
            if (tid < N_Q) ang_s[tid] = angv;
            __syncwarp();
            if (tid < N_Q) {
                if (t < SEQ - 1) angv = angb[(t + 1) * N_Q + tid];   // prefetch next step
                float x = bdt_s[tid];
#pragma unroll
                for (int v = 0; v < N_Q; v++) x = fmaf(Mdt_s[tid * 6 + v], ang_s[v], x);
                float sp = (x > 15.f) ? x : log1pf(__expf(x));
                float dt = tanhf(sp) * PI_F;
                dts_s[tid] = dt;
                float ph = ang_s[tid] * dt;
                __sincosf(ph, &ps_s[tid], &pc_s[tid]);
                __sincosf(0.5f * h_s[tid], &hs_s[tid], &hc_s[tid]);
            }
        }
        __syncthreads();

        // ---- Phase B: build state after RY(h) + QSVT (threads 0..63) ----
        if (tid < NSTATE) {
            int j = tid;
            float th = 0.f;
#pragma unroll
            for (int w = 0; w < N_Q; w++) th = fmaf(A_sT[w * NSTATE + j], dts_s[w], th);
            int sj = src_s[j];
            float r = 1.f;
#pragma unroll
            for (int w = 0; w < N_Q; w++) r *= ((sj >> (5 - w)) & 1) ? hs_s[w] : hc_s[w];
            float sn, cs;
            __sincosf(th, &sn, &cs);
            s_sh[((j & 31) << 1) | (j >> 5)] = make_float2(r * cs, -r * sn);
        }
        __syncthreads();

        // ---- Phase C: 64x64 complex matvec, U in registers ----
        float accx = 0.f, accy = 0.f;
        {
            const int half = tid & 1;
#pragma unroll
            for (int jj = 0; jj < 32; jj++) {
                float2 u  = ureg[jj];
                float2 sv = s_sh[(jj << 1) | half];
                accx = fmaf(u.x, sv.x, fmaf(-u.y, sv.y, accx));
                accy = fmaf(u.x, sv.y, fmaf(u.y, sv.x, accy));
            }
            accx += __shfl_xor_sync(0xffffffffu, accx, 1);
            accy += __shfl_xor_sync(0xffffffffu, accy, 1);
            if (!(tid & 1)) a_sh[tid >> 1] = make_float2(accx, accy);
        }
        __syncthreads();

        // ---- Phase D: measurement partials + 2-warp reduction (threads 0..63) ----
        if (tid < NSTATE) {
            const int k = tid;
            float2 a = a_sh[k];
            float pme = a.x * a.x + a.y * a.y;
            float part[18];
#pragma unroll
            for (int w = 0; w < N_Q; w++) {
                int m = 1 << (5 - w);
                bool bit = (k & m) != 0;
                part[w] = bit ? -pme : pme;                    // Z sum
                if (!bit) {
                    float2 pa = a_sh[k | m];
                    part[6 + w]  = a.x * pa.x + a.y * pa.y;    // Re conj(a0)*a1
                    part[12 + w] = a.x * pa.y - a.y * pa.x;    // Im conj(a0)*a1
                } else {
                    part[6 + w] = 0.f;
                    part[12 + w] = 0.f;
                }
            }
#pragma unroll
            for (int off = 16; off > 0; off >>= 1)
#pragma unroll
                for (int q = 0; q < 18; q++)
                    part[q] += __shfl_xor_sync(0xffffffffu, part[q], off);
            if ((tid & 31) == 0)
                for (int q = 0; q < 18; q++) red_s[tid >> 5][q] = part[q];
        }
        __syncthreads();

        // ---- Phase E: rotated-operator measurements, h update, output (threads 0..17) ----
        if (tid < 18) {
            const int j = tid;
            const int w = j % 6;
            float zs = red_s[0][w]      + red_s[1][w];
            float tr = red_s[0][6 + w]  + red_s[1][6 + w];
            float ti = red_s[0][12 + w] + red_s[1][12 + w];
            float c = pc_s[w], s = ps_s[w];
            float meas;
            if (j < 6)       meas = fmaf(s, zs,  2.f * c * tr);   // <X>
            else if (j < 12) meas = 2.f * ti;                     // <Y>
            else {           meas = fmaf(c, zs, -2.f * s * tr);   // <Z>
                             h_s[w] = meas; }
            float cw = 0.f;
#pragma unroll
            for (int v = 0; v < N_Q; v++) cw = fmaf(Mcw_s[j * 6 + v], ang_s[v], cw);
            out[((size_t)b * SEQ + t) * 18 + j] = fmaf(cw, meas, D_s[j] * ang_s[w]);
        }
        __syncthreads();
    }
}

extern "C" void kernel_launch(void* const* d_in, const int* in_sizes, int n_in,
                              void* d_out, int out_size)
{
    const float* angles = (const float*)d_in[0];   // (256,512,6)
    const float* Wx     = (const float*)d_in[1];   // (15,6)
    const float* Wdt    = (const float*)d_in[2];   // (6,3)
    const float* bdt    = (const float*)d_in[3];   // (6)
    const float* poly   = (const float*)d_in[4];   // (4)
    const float* qsvt   = (const float*)d_in[5];   // (18)
    const float* cp     = (const float*)d_in[6];   // (60)
    const float* D      = (const float*)d_in[7];   // (18)
    const float* Wc     = (const float*)d_in[8];   // (18,6)
    float* out = (float*)d_out;                    // (256,512,18)

    qm_setup<<<1, 128>>>(Wx, Wdt, poly, qsvt, cp, Wc);
    qm_main<<<BATCH, 128>>>(angles, bdt, D, out);
}